// round 13
// baseline (speedup 1.0000x reference)
#include <cuda_runtime.h>
#include <cstdint>

#define T_STEPS 512

// Scratch (allocation-free rule: __device__ globals)
// proj[bucket][lane] = (Pi*0.5, Pf*0.5, Pc*1.0, Po*0.5)  (0.5 = sigmoid-via-tanh prescale)
__device__ __align__(16) float g_proj2[4096 * 32 * 4];
// Rpack: ull at ((c*16 + j)*32 + lane) = (R[2j][col]*s_c, R[2j+1][col]*s_c), col = c*32+lane
__device__ __align__(16) unsigned long long g_R[4 * 16 * 32];

// ---------- packed f32x2 helpers ----------
__device__ __forceinline__ void fma2(unsigned long long& acc, unsigned long long a, unsigned long long b) {
    asm("fma.rn.f32x2 %0, %1, %2, %0;" : "+l"(acc) : "l"(a), "l"(b));
}
__device__ __forceinline__ unsigned long long pk2(float lo, float hi) {
    unsigned long long r;
    asm("mov.b64 %0, {%1, %2};" : "=l"(r) : "f"(lo), "f"(hi));
    return r;
}
__device__ __forceinline__ void unpk2(unsigned long long v, float& lo, float& hi) {
    asm("mov.b64 {%0, %1}, %2;" : "=f"(lo), "=f"(hi) : "l"(v));
}
__device__ __forceinline__ float ftanh(float x) {
    float y; asm("tanh.approx.f32 %0, %1;" : "=f"(y) : "f"(x)); return y;
}
__device__ __forceinline__ float sigp(float xs) {   // sigmoid, input prescaled x0.5
    return fmaf(ftanh(xs), 0.5f, 0.5f);
}

// ---------- merged prep (unchanged — known correct) ----------
__global__ void prep_all(const float* __restrict__ emb, const float* __restrict__ K,
                         const float* __restrict__ R, int nbuckets) {
    int idx = blockIdx.x * blockDim.x + threadIdx.x;
    if (idx < 4 * 16 * 32) {
        int lane = idx & 31, j = (idx >> 5) & 15, c = idx >> 9;
        int col = c * 32 + lane;
        float s = (c == 2) ? 1.0f : 0.5f;
        float lo = R[(2 * j) * 128 + col] * s;
        float hi = R[(2 * j + 1) * 128 + col] * s;
        unsigned long long v;
        asm("mov.b64 %0, {%1, %2};" : "=l"(v) : "f"(lo), "f"(hi));
        g_R[idx] = v;
    }
    int id = idx >> 5, l = idx & 31;
    if (id >= nbuckets) return;
    float a = 0.f, b = 0.f, c = 0.f, d = 0.f;
#pragma unroll
    for (int e = 0; e < 16; e++) {
        float xv = emb[id * 16 + e];
        const float* kr = K + e * 128 + l;
        a = fmaf(xv, kr[0],  a);
        b = fmaf(xv, kr[32], b);
        c = fmaf(xv, kr[64], c);
        d = fmaf(xv, kr[96], d);
    }
    *(float4*)&g_proj2[idx * 4] = make_float4(a * 0.5f, b * 0.5f, c, d * 0.5f);
}

// One LSTM step (R8 structure): consumes prefetched p, prefetches pn for the NEXT
// step (full-step L2 cover), reads hb[RB], writes hb[WB]. No syncwarp (lanes
// provably convergent; compiler barrier orders STS before next step's LDS).
// IDN = warp-uniform bucket id for the NEXT step.
#define STEP_BODY(RB, WB, IDN)                                                 \
    {                                                                          \
        float4 pn = Pp[(IDN) * 32 + lane];   /* prefetch next-step proj */     \
        unsigned long long a0 = pk2(p.x, 0.f);                                 \
        unsigned long long a1 = pk2(p.y, 0.f);                                 \
        unsigned long long a2 = pk2(p.z, 0.f);                                 \
        unsigned long long a3 = pk2(p.w, 0.f);                                 \
        const ulonglong2* hp = (const ulonglong2*)&hb[RB][0];                  \
        _Pragma("unroll")                                                      \
        for (int k = 0; k < 8; k++) {                                          \
            ulonglong2 hv = hp[k];       /* broadcast LDS.128 */               \
            fma2(a0, RW[0][2 * k], hv.x);                                      \
            fma2(a1, RW[1][2 * k], hv.x);                                      \
            fma2(a2, RW[2][2 * k], hv.x);                                      \
            fma2(a3, RW[3][2 * k], hv.x);                                      \
            fma2(a0, RW[0][2 * k + 1], hv.y);                                  \
            fma2(a1, RW[1][2 * k + 1], hv.y);                                  \
            fma2(a2, RW[2][2 * k + 1], hv.y);                                  \
            fma2(a3, RW[3][2 * k + 1], hv.y);                                  \
        }                                                                      \
        float lo, hi;                                                          \
        unpk2(a0, lo, hi); float zi = lo + hi;                                 \
        unpk2(a1, lo, hi); float zf = lo + hi;                                 \
        unpk2(a2, lo, hi); float zc = lo + hi;                                 \
        unpk2(a3, lo, hi); float zo = lo + hi;                                 \
        float ig = sigp(zi);                                                   \
        float fg = sigp(zf);                                                   \
        float og = sigp(zo);                                                   \
        float gg = ftanh(zc);                                                  \
        cst = fmaf(fg, cst, ig * gg);                                          \
        float h = og * ftanh(cst);                                             \
        hb[WB][lane] = h;                                                      \
        asm volatile("" ::: "memory");                                         \
        p = pn;                                                                \
    }

// ---------- main: ONE warp per CTA; R8 loop + no-syncwarp + static 2-step unroll --
__global__ __launch_bounds__(32, 12) void lstm_main(
    const int* __restrict__ ids,
    const float* __restrict__ w1, const float* __restrict__ b1,
    const float* __restrict__ w2, const float* __restrict__ b2,
    float* __restrict__ out, int B)
{
    __shared__ __align__(16) float hb[2][32];      // double-buffered h
    const int lane = threadIdx.x & 31;
    const int b = blockIdx.x;
    if (b >= B) return;

    // weights: per lane, 4 owned cols x 16 j-pairs (prescaled) = 128 regs
    unsigned long long RW[4][16];
#pragma unroll
    for (int c = 0; c < 4; c++)
#pragma unroll
        for (int j = 0; j < 16; j++)
            RW[c][j] = g_R[(c * 16 + j) * 32 + lane];

    const float4* Pp = (const float4*)g_proj2;
    const int* idrow = ids + b * T_STEPS;
    // double-buffered 32-step id blocks (no load-to-use stall at block boundary)
    int cur = idrow[lane];
    int nxt = idrow[32 + lane];

    int id0 = __shfl_sync(0xffffffffu, cur, 0);
    float4 p = Pp[id0 * 32 + lane];                // proj for step 0 (prescaled)

    hb[0][lane] = 0.f;                             // h_0 = 0
    __syncwarp();

    float cst = 0.f;
    for (int t = 0; t < T_STEPS; t += 2) {
        // ---- even step t: reads hb[0] writes hb[1]; next = t+1 (odd, no refill)
        {
            int idn = __shfl_sync(0xffffffffu, cur, (t + 1) & 31);
            STEP_BODY(0, 1, idn);
        }
        // ---- odd step t+1: reads hb[1] writes hb[0]; next = t+2 (even, may refill)
        {
            int tn = t + 2;
            int j32 = tn & 31;
            if (j32 == 0 && tn < T_STEPS) {
                cur = nxt;
                if (tn + 32 < T_STEPS) nxt = idrow[tn + 32 + lane];
            }
            int idn = __shfl_sync(0xffffffffu, cur, j32);
            STEP_BODY(1, 0, idn);
        }
    }

    // head: y = relu(h @ w1 + b1) @ w2 + b2  (final h in hb[0], T even)
    __syncwarp();
    float s = b1[lane];
#pragma unroll
    for (int l = 0; l < 32; l++)
        s = fmaf(hb[0][l], w1[l * 32 + lane], s);
    float r = fmaxf(s, 0.f) * w2[lane];
#pragma unroll
    for (int off = 16; off; off >>= 1)
        r += __shfl_xor_sync(0xffffffffu, r, off);
    if (lane == 0) out[b] = r + b2[0];
}

extern "C" void kernel_launch(void* const* d_in, const int* in_sizes, int n_in,
                              void* d_out, int out_size)
{
    const int*   ids  = (const int*)d_in[0];
    const float* emb  = (const float*)d_in[1];
    const float* kern = (const float*)d_in[2];
    const float* rec  = (const float*)d_in[3];
    const float* w1   = (const float*)d_in[4];
    const float* b1   = (const float*)d_in[5];
    const float* w2   = (const float*)d_in[6];
    const float* b2   = (const float*)d_in[7];

    int B = in_sizes[0] / T_STEPS;
    int nbuckets = in_sizes[1] / 16;
    if (nbuckets > 4096) nbuckets = 4096;

    int prep_threads = nbuckets * 32;
    if (prep_threads < 2048) prep_threads = 2048;
    prep_all<<<(prep_threads + 127) / 128, 128>>>(emb, kern, rec, nbuckets);
    lstm_main<<<B, 32>>>(ids, w1, b1, w2, b2, (float*)d_out, B);
}

// round 14
// speedup vs baseline: 1.0616x; 1.0616x over previous
#include <cuda_runtime.h>
#include <cstdint>

#define T_STEPS 512

// Scratch (allocation-free rule: __device__ globals)
// proj[bucket][lane] = (Pi*0.5, Pf*0.5, Pc*1.0, Po*0.5)  (0.5 = sigmoid-via-tanh prescale)
__device__ __align__(16) float g_proj2[4096 * 32 * 4];
// Rpack: ull at ((c*16 + j)*32 + lane) = (R[2j][col]*s_c, R[2j+1][col]*s_c), col = c*32+lane
__device__ __align__(16) unsigned long long g_R[4 * 16 * 32];

// ---------- packed f32x2 helpers ----------
__device__ __forceinline__ void fma2(unsigned long long& acc, unsigned long long a, unsigned long long b) {
    asm("fma.rn.f32x2 %0, %1, %2, %0;" : "+l"(acc) : "l"(a), "l"(b));
}
__device__ __forceinline__ unsigned long long pk2(float lo, float hi) {
    unsigned long long r;
    asm("mov.b64 %0, {%1, %2};" : "=l"(r) : "f"(lo), "f"(hi));
    return r;
}
__device__ __forceinline__ void unpk2(unsigned long long v, float& lo, float& hi) {
    asm("mov.b64 {%0, %1}, %2;" : "=f"(lo), "=f"(hi) : "l"(v));
}
__device__ __forceinline__ float ftanh(float x) {
    float y; asm("tanh.approx.f32 %0, %1;" : "=f"(y) : "f"(x)); return y;
}
__device__ __forceinline__ float sigp(float xs) {   // sigmoid, input prescaled x0.5
    return fmaf(ftanh(xs), 0.5f, 0.5f);
}

// ---------- merged prep (unchanged — known correct) ----------
__global__ void prep_all(const float* __restrict__ emb, const float* __restrict__ K,
                         const float* __restrict__ R, int nbuckets) {
    int idx = blockIdx.x * blockDim.x + threadIdx.x;
    if (idx < 4 * 16 * 32) {
        int lane = idx & 31, j = (idx >> 5) & 15, c = idx >> 9;
        int col = c * 32 + lane;
        float s = (c == 2) ? 1.0f : 0.5f;
        float lo = R[(2 * j) * 128 + col] * s;
        float hi = R[(2 * j + 1) * 128 + col] * s;
        unsigned long long v;
        asm("mov.b64 %0, {%1, %2};" : "=l"(v) : "f"(lo), "f"(hi));
        g_R[idx] = v;
    }
    int id = idx >> 5, l = idx & 31;
    if (id >= nbuckets) return;
    float a = 0.f, b = 0.f, c = 0.f, d = 0.f;
#pragma unroll
    for (int e = 0; e < 16; e++) {
        float xv = emb[id * 16 + e];
        const float* kr = K + e * 128 + l;
        a = fmaf(xv, kr[0],  a);
        b = fmaf(xv, kr[32], b);
        c = fmaf(xv, kr[64], c);
        d = fmaf(xv, kr[96], d);
    }
    *(float4*)&g_proj2[idx * 4] = make_float4(a * 0.5f, b * 0.5f, c, d * 0.5f);
}

// ---------- main: ONE warp per CTA (fine-grained scheduling), R3 inner loop ----------
__global__ __launch_bounds__(32, 12) void lstm_main(
    const int* __restrict__ ids,
    const float* __restrict__ w1, const float* __restrict__ b1,
    const float* __restrict__ w2, const float* __restrict__ b2,
    float* __restrict__ out, int B)
{
    __shared__ __align__(16) float hb[2][32];      // double-buffered h
    const int lane = threadIdx.x & 31;
    const int b = blockIdx.x;
    if (b >= B) return;

    // weights: per lane, 4 owned cols x 16 j-pairs (prescaled) = 128 regs
    unsigned long long RW[4][16];
#pragma unroll
    for (int c = 0; c < 4; c++)
#pragma unroll
        for (int j = 0; j < 16; j++)
            RW[c][j] = g_R[(c * 16 + j) * 32 + lane];

    const float4* Pp = (const float4*)g_proj2;
    const int* idrow = ids + b * T_STEPS;
    // double-buffered 32-step id blocks (no load-to-use stall at block boundary)
    int cur = idrow[lane];
    int nxt = idrow[32 + lane];

    int id0 = __shfl_sync(0xffffffffu, cur, 0);
    float4 p = Pp[id0 * 32 + lane];                // proj for step 0 (prescaled)

    hb[0][lane] = 0.f;                             // h_0 = 0
    __syncwarp();

    float cst = 0.f;
    for (int t = 0; t < T_STEPS; t++) {
        // prefetch proj for step t+1 (hidden behind this step's math)
        int tn = t + 1;
        int j32 = tn & 31;
        if (j32 == 0 && tn < T_STEPS) {
            cur = nxt;
            if (tn + 32 < T_STEPS) nxt = idrow[tn + 32 + lane];
        }
        int idn = __shfl_sync(0xffffffffu, cur, j32);
        float4 pn = Pp[idn * 32 + lane];

        // proj folded into acc init (even half) — saves tail FADDs
        unsigned long long a0 = pk2(p.x, 0.f);
        unsigned long long a1 = pk2(p.y, 0.f);
        unsigned long long a2 = pk2(p.z, 0.f);
        unsigned long long a3 = pk2(p.w, 0.f);
        const ulonglong2* hp = (const ulonglong2*)&hb[t & 1][0];
#pragma unroll
        for (int k = 0; k < 8; k++) {
            ulonglong2 hv = hp[k];              // (h4k,h4k+1),(h4k+2,h4k+3) broadcast LDS.128
            fma2(a0, RW[0][2 * k], hv.x);
            fma2(a1, RW[1][2 * k], hv.x);
            fma2(a2, RW[2][2 * k], hv.x);
            fma2(a3, RW[3][2 * k], hv.x);
            fma2(a0, RW[0][2 * k + 1], hv.y);
            fma2(a1, RW[1][2 * k + 1], hv.y);
            fma2(a2, RW[2][2 * k + 1], hv.y);
            fma2(a3, RW[3][2 * k + 1], hv.y);
        }
        float lo, hi;
        unpk2(a0, lo, hi); float zi = lo + hi;
        unpk2(a1, lo, hi); float zf = lo + hi;
        unpk2(a2, lo, hi); float zc = lo + hi;
        unpk2(a3, lo, hi); float zo = lo + hi;

        float ig = sigp(zi);
        float fg = sigp(zf);
        float og = sigp(zo);
        float gg = ftanh(zc);
        cst = fmaf(fg, cst, ig * gg);
        float h = og * ftanh(cst);

        hb[tn & 1][lane] = h;
        __syncwarp();
        p = pn;
    }

    // head: y = relu(h @ w1 + b1) @ w2 + b2  (final h in hb[0], T even)
    float s = b1[lane];
#pragma unroll
    for (int l = 0; l < 32; l++)
        s = fmaf(hb[0][l], w1[l * 32 + lane], s);
    float r = fmaxf(s, 0.f) * w2[lane];
#pragma unroll
    for (int off = 16; off; off >>= 1)
        r += __shfl_xor_sync(0xffffffffu, r, off);
    if (lane == 0) out[b] = r + b2[0];
}

extern "C" void kernel_launch(void* const* d_in, const int* in_sizes, int n_in,
                              void* d_out, int out_size)
{
    const int*   ids  = (const int*)d_in[0];
    const float* emb  = (const float*)d_in[1];
    const float* kern = (const float*)d_in[2];
    const float* rec  = (const float*)d_in[3];
    const float* w1   = (const float*)d_in[4];
    const float* b1   = (const float*)d_in[5];
    const float* w2   = (const float*)d_in[6];
    const float* b2   = (const float*)d_in[7];

    int B = in_sizes[0] / T_STEPS;
    int nbuckets = in_sizes[1] / 16;
    if (nbuckets > 4096) nbuckets = 4096;

    int prep_threads = nbuckets * 32;
    if (prep_threads < 2048) prep_threads = 2048;
    prep_all<<<(prep_threads + 127) / 128, 128>>>(emb, kern, rec, nbuckets);
    lstm_main<<<B, 32>>>(ids, w1, b1, w2, b2, (float*)d_out, B);
}

// round 15
// speedup vs baseline: 1.0648x; 1.0030x over previous
#include <cuda_runtime.h>
#include <cstdint>

#define T_STEPS 512

// Scratch (allocation-free rule: __device__ globals)
// proj[bucket][lane] = (Pi*0.5, Pf*0.5, Pc*1.0, Po*0.5)  (0.5 = sigmoid-via-tanh prescale)
__device__ __align__(16) float g_proj2[4096 * 32 * 4];
// Rpack: ull at ((c*16 + j)*32 + lane) = (R[2j][col]*s_c, R[2j+1][col]*s_c), col = c*32+lane
__device__ __align__(16) unsigned long long g_R[4 * 16 * 32];

// ---------- packed f32x2 helpers ----------
__device__ __forceinline__ void fma2(unsigned long long& acc, unsigned long long a, unsigned long long b) {
    asm("fma.rn.f32x2 %0, %1, %2, %0;" : "+l"(acc) : "l"(a), "l"(b));
}
__device__ __forceinline__ unsigned long long pk2(float lo, float hi) {
    unsigned long long r;
    asm("mov.b64 %0, {%1, %2};" : "=l"(r) : "f"(lo), "f"(hi));
    return r;
}
__device__ __forceinline__ void unpk2(unsigned long long v, float& lo, float& hi) {
    asm("mov.b64 {%0, %1}, %2;" : "=f"(lo), "=f"(hi) : "l"(v));
}
__device__ __forceinline__ float ftanh(float x) {
    float y; asm("tanh.approx.f32 %0, %1;" : "=f"(y) : "f"(x)); return y;
}
__device__ __forceinline__ float sigp(float xs) {   // sigmoid, input prescaled x0.5
    return fmaf(ftanh(xs), 0.5f, 0.5f);
}

// ---------- merged prep (unchanged — known correct) ----------
__global__ void prep_all(const float* __restrict__ emb, const float* __restrict__ K,
                         const float* __restrict__ R, int nbuckets) {
    int idx = blockIdx.x * blockDim.x + threadIdx.x;
    if (idx < 4 * 16 * 32) {
        int lane = idx & 31, j = (idx >> 5) & 15, c = idx >> 9;
        int col = c * 32 + lane;
        float s = (c == 2) ? 1.0f : 0.5f;
        float lo = R[(2 * j) * 128 + col] * s;
        float hi = R[(2 * j + 1) * 128 + col] * s;
        unsigned long long v;
        asm("mov.b64 %0, {%1, %2};" : "=l"(v) : "f"(lo), "f"(hi));
        g_R[idx] = v;
    }
    int id = idx >> 5, l = idx & 31;
    if (id >= nbuckets) return;
    float a = 0.f, b = 0.f, c = 0.f, d = 0.f;
#pragma unroll
    for (int e = 0; e < 16; e++) {
        float xv = emb[id * 16 + e];
        const float* kr = K + e * 128 + l;
        a = fmaf(xv, kr[0],  a);
        b = fmaf(xv, kr[32], b);
        c = fmaf(xv, kr[64], c);
        d = fmaf(xv, kr[96], d);
    }
    *(float4*)&g_proj2[idx * 4] = make_float4(a * 0.5f, b * 0.5f, c, d * 0.5f);
}

// ---------- main: ONE warp per CTA (fine-grained scheduling), R3 inner loop ----------
__global__ __launch_bounds__(32, 12) void lstm_main(
    const int* __restrict__ ids,
    const float* __restrict__ w1, const float* __restrict__ b1,
    const float* __restrict__ w2, const float* __restrict__ b2,
    float* __restrict__ out, int B)
{
    __shared__ __align__(16) float hb[2][32];      // double-buffered h
    const int lane = threadIdx.x & 31;
    const int b = blockIdx.x;
    if (b >= B) return;

    // weights: per lane, 4 owned cols x 16 j-pairs (prescaled) = 128 regs
    unsigned long long RW[4][16];
#pragma unroll
    for (int c = 0; c < 4; c++)
#pragma unroll
        for (int j = 0; j < 16; j++)
            RW[c][j] = g_R[(c * 16 + j) * 32 + lane];

    const float4* Pp = (const float4*)g_proj2;
    const int* idrow = ids + b * T_STEPS;
    // double-buffered 32-step id blocks (no load-to-use stall at block boundary)
    int cur = idrow[lane];
    int nxt = idrow[32 + lane];

    int id0 = __shfl_sync(0xffffffffu, cur, 0);
    float4 p = Pp[id0 * 32 + lane];                // proj for step 0 (prescaled)

    hb[0][lane] = 0.f;                             // h_0 = 0
    __syncwarp();

    float cst = 0.f;
    for (int t = 0; t < T_STEPS; t++) {
        // prefetch proj for step t+1 (hidden behind this step's math)
        int tn = t + 1;
        int j32 = tn & 31;
        if (j32 == 0 && tn < T_STEPS) {
            cur = nxt;
            if (tn + 32 < T_STEPS) nxt = idrow[tn + 32 + lane];
        }
        int idn = __shfl_sync(0xffffffffu, cur, j32);
        float4 pn = Pp[idn * 32 + lane];

        // proj folded into acc init (even half) — saves tail FADDs
        unsigned long long a0 = pk2(p.x, 0.f);
        unsigned long long a1 = pk2(p.y, 0.f);
        unsigned long long a2 = pk2(p.z, 0.f);
        unsigned long long a3 = pk2(p.w, 0.f);
        const ulonglong2* hp = (const ulonglong2*)&hb[t & 1][0];
#pragma unroll
        for (int k = 0; k < 8; k++) {
            ulonglong2 hv = hp[k];              // (h4k,h4k+1),(h4k+2,h4k+3) broadcast LDS.128
            fma2(a0, RW[0][2 * k], hv.x);
            fma2(a1, RW[1][2 * k], hv.x);
            fma2(a2, RW[2][2 * k], hv.x);
            fma2(a3, RW[3][2 * k], hv.x);
            fma2(a0, RW[0][2 * k + 1], hv.y);
            fma2(a1, RW[1][2 * k + 1], hv.y);
            fma2(a2, RW[2][2 * k + 1], hv.y);
            fma2(a3, RW[3][2 * k + 1], hv.y);
        }
        float lo, hi;
        unpk2(a0, lo, hi); float zi = lo + hi;
        unpk2(a1, lo, hi); float zf = lo + hi;
        unpk2(a2, lo, hi); float zc = lo + hi;
        unpk2(a3, lo, hi); float zo = lo + hi;

        float ig = sigp(zi);
        float fg = sigp(zf);
        float og = sigp(zo);
        float gg = ftanh(zc);
        cst = fmaf(fg, cst, ig * gg);
        float h = og * ftanh(cst);

        hb[tn & 1][lane] = h;
        __syncwarp();
        p = pn;
    }

    // head: y = relu(h @ w1 + b1) @ w2 + b2  (final h in hb[0], T even)
    float s = b1[lane];
#pragma unroll
    for (int l = 0; l < 32; l++)
        s = fmaf(hb[0][l], w1[l * 32 + lane], s);
    float r = fmaxf(s, 0.f) * w2[lane];
#pragma unroll
    for (int off = 16; off; off >>= 1)
        r += __shfl_xor_sync(0xffffffffu, r, off);
    if (lane == 0) out[b] = r + b2[0];
}

extern "C" void kernel_launch(void* const* d_in, const int* in_sizes, int n_in,
                              void* d_out, int out_size)
{
    const int*   ids  = (const int*)d_in[0];
    const float* emb  = (const float*)d_in[1];
    const float* kern = (const float*)d_in[2];
    const float* rec  = (const float*)d_in[3];
    const float* w1   = (const float*)d_in[4];
    const float* b1   = (const float*)d_in[5];
    const float* w2   = (const float*)d_in[6];
    const float* b2   = (const float*)d_in[7];

    int B = in_sizes[0] / T_STEPS;
    int nbuckets = in_sizes[1] / 16;
    if (nbuckets > 4096) nbuckets = 4096;

    int prep_threads = nbuckets * 32;
    if (prep_threads < 2048) prep_threads = 2048;
    prep_all<<<(prep_threads + 127) / 128, 128>>>(emb, kern, rec, nbuckets);
    lstm_main<<<B, 32>>>(ids, w1, b1, w2, b2, (float*)d_out, B);
}